// round 9
// baseline (speedup 1.0000x reference)
#include <cuda_runtime.h>
#include <cstdint>
#include <math.h>

#define NPIX 41472      // 8*72*72
#define TT 64

typedef unsigned long long u64;

// ---------------- device scratch (no allocations allowed) ----------------
__device__ float g_h[NPIX * 16];
__device__ float g_lam[2 * NPIX];
__device__ float g_un[NPIX];
__device__ float g_pre[NPIX];
__device__ float g_xcur[NPIX * 16];
__device__ float g_xn[NPIX * 16];

// ---------------- packed f32x2 helpers (sm_103a FFMA2 path) ----------------
__device__ __forceinline__ u64 pk2(float lo, float hi) {
    u64 r; asm("mov.b64 %0, {%1, %2};" : "=l"(r) : "f"(lo), "f"(hi)); return r;
}
__device__ __forceinline__ u64 dup2(float v) { return pk2(v, v); }
__device__ __forceinline__ void fma2(u64& d, u64 a, u64 b) {
    asm("fma.rn.f32x2 %0, %1, %2, %0;" : "+l"(d) : "l"(a), "l"(b));
}
__device__ __forceinline__ float2 upk(u64 v) {
    float2 r; asm("mov.b64 {%0, %1}, %2;" : "=f"(r.x), "=f"(r.y) : "l"(v)); return r;
}

// ---------------- threefry-2x32 (JAX-compatible) ----------------
__device__ __forceinline__ uint2 d_threefry(uint32_t k0, uint32_t k1,
                                            uint32_t x0, uint32_t x1) {
    uint32_t ks2 = k0 ^ k1 ^ 0x1BD11BDAu;
    x0 += k0; x1 += k1;
#define TFR(r) { x0 += x1; x1 = __funnelshift_l(x1, x1, (r)); x1 ^= x0; }
    TFR(13) TFR(15) TFR(26) TFR(6)  x0 += k1;  x1 += ks2 + 1u;
    TFR(17) TFR(29) TFR(16) TFR(24) x0 += ks2; x1 += k0 + 2u;
    TFR(13) TFR(15) TFR(26) TFR(6)  x0 += k0;  x1 += k1 + 3u;
    TFR(17) TFR(29) TFR(16) TFR(24) x0 += k1;  x1 += ks2 + 4u;
    TFR(13) TFR(15) TFR(26) TFR(6)  x0 += ks2; x1 += k0 + 5u;
#undef TFR
    return make_uint2(x0, x1);
}

static void h_threefry(uint32_t k0, uint32_t k1, uint32_t x0, uint32_t x1,
                       uint32_t* o0, uint32_t* o1) {
    uint32_t ks2 = k0 ^ k1 ^ 0x1BD11BDAu;
    x0 += k0; x1 += k1;
    const int ra[4] = {13, 15, 26, 6}, rb[4] = {17, 29, 16, 24};
    uint32_t ks[3] = {k0, k1, ks2};
    for (int i = 0; i < 5; i++) {
        const int* rr = (i & 1) ? rb : ra;
        for (int r = 0; r < 4; r++) {
            x0 += x1;
            x1 = (x1 << rr[r]) | (x1 >> (32 - rr[r]));
            x1 ^= x0;
        }
        x0 += ks[(i + 1) % 3];
        x1 += ks[(i + 2) % 3] + (uint32_t)(i + 1);
    }
    *o0 = x0; *o1 = x1;
}

// -------- perceive one (pixel, c4-quad): ctr + 2 sobel quads (k_perc order) --------
__device__ __forceinline__ void perc_quad(const float* __restrict__ x,
                                          int img, int h, int w, int c4,
                                          float4& ctr, float4& s1, float4& s2) {
    const float W1[3][3] = {{-0.125f, -0.25f, -0.125f},
                            { 0.f,     0.f,    0.f   },
                            { 0.125f,  0.25f,  0.125f}};
    const float W2[3][3] = {{-0.125f, 0.f, 0.125f},
                            {-0.25f,  0.f, 0.25f },
                            {-0.125f, 0.f, 0.125f}};
    ctr = __ldg((const float4*)&x[((img * 5184 + h * 72 + w) << 4) + c4]);
    s1 = make_float4(0.f, 0.f, 0.f, 0.f);
    s2 = make_float4(0.f, 0.f, 0.f, 0.f);
#pragma unroll
    for (int i = 0; i < 3; i++) {
        int hh = h + i - 1;
        if ((unsigned)hh >= 72u) continue;
#pragma unroll
        for (int j = 0; j < 3; j++) {
            int ww = w + j - 1;
            if ((unsigned)ww >= 72u) continue;
            float4 v = __ldg((const float4*)&x[((img * 5184 + hh * 72 + ww) << 4) + c4]);
            float w1 = W1[i][j], w2 = W2[i][j];
            s1.x = fmaf(v.x, w1, s1.x); s1.y = fmaf(v.y, w1, s1.y);
            s1.z = fmaf(v.z, w1, s1.z); s1.w = fmaf(v.w, w1, s1.w);
            s2.x = fmaf(v.x, w2, s2.x); s2.y = fmaf(v.y, w2, s2.y);
            s2.z = fmaf(v.z, w2, s2.z); s2.w = fmaf(v.w, w2, s2.w);
        }
    }
}

// ============ fused kernel: perc+c1 (blocks [0,n_c1)) | perc+update (rest) ============
// c1 path:  block = 216 pixels (3 rows), smem s_p[5][72][48] = 69120 B
// upd path: block = 128 pixels; s_pT[48][128] (24576) then s_h[128][132] overlay
//           (67584) + s_dx (8192) = 75776 B
#define K2_SMEM 75776

__global__ void __launch_bounds__(256, 2) k_main(
    int n_c1,
    const float* __restrict__ xext, int use_ext,
    const float* __restrict__ c1w, const float* __restrict__ c1b,
    const float* __restrict__ f0w, const float* __restrict__ f0b,
    const float* __restrict__ f1w,
    float* __restrict__ upd_slot, int rsel, uint32_t key0, uint32_t key1)
{
    extern __shared__ float sm[];
    int t = threadIdx.x;
    const float* __restrict__ x = use_ext ? xext : g_xcur;

    if ((int)blockIdx.x < n_c1) {
        // ---------------- conv1 path: 216 pixels (3 rows) / block ----------------
        int bk = blockIdx.x;
        int img = bk / 24, chunk = bk - img * 24;
        int r0 = chunk * 3;
        int pbase = img * 5184 + r0 * 72;

        float* s_p = sm;                    // [5][72][48], perc rows r0-1..r0+3
        for (int i = t; i < 1440; i += 256) {          // (row, pix, c4g)
            int row = i / 288;
            int rem = i - row * 288;
            int pix = rem >> 2;
            int c4 = (rem & 3) * 4;
            int gr = r0 - 1 + row;
            float4 ctr = make_float4(0.f, 0.f, 0.f, 0.f);
            float4 s1  = make_float4(0.f, 0.f, 0.f, 0.f);
            float4 s2  = make_float4(0.f, 0.f, 0.f, 0.f);
            if ((unsigned)gr < 72u)
                perc_quad(x, img, gr, pix, c4, ctr, s1, s2);
            float* dst = &s_p[(row * 72 + pix) * 48];
            *(float4*)&dst[c4]      = ctr;
            *(float4*)&dst[16 + c4] = s1;
            *(float4*)&dst[32 + c4] = s2;
        }
        __syncthreads();

        if (t < 216) {
            int og = t & 3, pg = t >> 2;        // pg 0..53
            int o0 = og * 4;
            int lr = pg / 18;                   // local out row 0..2
            int c0 = (pg - lr * 18) * 4;        // starting col, multiple of 4

            float4 b4 = __ldg((const float4*)&c1b[o0]);
            u64 acc[4][2];
#pragma unroll
            for (int s = 0; s < 4; s++) {
                acc[s][0] = pk2(b4.x, b4.y);
                acc[s][1] = pk2(b4.z, b4.w);
            }

            for (int i = 0; i < 3; i++) {
                const float* __restrict__ prow = &s_p[(lr + i) * 72 * 48];
#pragma unroll
                for (int j = 0; j < 3; j++) {
                    int wbase = c0 + j - 1;
                    const ulonglong2* __restrict__ wp =
                        (const ulonglong2*)(c1w + (i * 3 + j) * 768 + o0);
#pragma unroll 4
                    for (int c4i = 0; c4i < 12; c4i++) {
                        ulonglong2 wq0 = __ldg(&wp[(c4i * 4 + 0) * 4]);
                        ulonglong2 wq1 = __ldg(&wp[(c4i * 4 + 1) * 4]);
                        ulonglong2 wq2 = __ldg(&wp[(c4i * 4 + 2) * 4]);
                        ulonglong2 wq3 = __ldg(&wp[(c4i * 4 + 3) * 4]);
#pragma unroll
                        for (int s = 0; s < 4; s++) {
                            int ww = wbase + s;
                            if ((unsigned)ww < 72u) {
                                float4 pv = *(const float4*)&prow[ww * 48 + c4i * 4];
                                u64 p0 = dup2(pv.x), p1 = dup2(pv.y);
                                u64 p2 = dup2(pv.z), p3 = dup2(pv.w);
                                fma2(acc[s][0], p0, wq0.x); fma2(acc[s][1], p0, wq0.y);
                                fma2(acc[s][0], p1, wq1.x); fma2(acc[s][1], p1, wq1.y);
                                fma2(acc[s][0], p2, wq2.x); fma2(acc[s][1], p2, wq2.y);
                                fma2(acc[s][0], p3, wq3.x); fma2(acc[s][1], p3, wq3.y);
                            }
                        }
                    }
                }
            }
#pragma unroll
            for (int s = 0; s < 4; s++) {
                float2 v0 = upk(acc[s][0]), v1 = upk(acc[s][1]);
                float4 o = make_float4(fmaxf(v0.x, 0.f), fmaxf(v0.y, 0.f),
                                       fmaxf(v1.x, 0.f), fmaxf(v1.y, 0.f));
                *(float4*)&g_h[(pbase + pg * 4 + s) * 16 + o0] = o;
            }
        }
    } else {
        // ---------------- update path: 128 pixels / block ----------------
        int P0 = ((int)blockIdx.x - n_c1) * 128;

        float* s_pT = sm;                   // [48][128] during phase 1
        float* s_h  = sm;                   // [128][132] phase 2 (overlays s_pT)
        float* s_dx = sm + 16896;           // [128][16]

        for (int i = t; i < 512; i += 256) {           // (pix, c4g)
            int pix = i >> 2, c4 = (i & 3) * 4;
            int gp = P0 + pix;
            int img = gp / 5184; int hw = gp - img * 5184;
            int h = hw / 72, w = hw - h * 72;
            float4 ctr, s1, s2;
            perc_quad(x, img, h, w, c4, ctr, s1, s2);
            s_pT[(c4 + 0) * 128 + pix] = ctr.x;
            s_pT[(c4 + 1) * 128 + pix] = ctr.y;
            s_pT[(c4 + 2) * 128 + pix] = ctr.z;
            s_pT[(c4 + 3) * 128 + pix] = ctr.w;
            s_pT[(16 + c4 + 0) * 128 + pix] = s1.x;
            s_pT[(16 + c4 + 1) * 128 + pix] = s1.y;
            s_pT[(16 + c4 + 2) * 128 + pix] = s1.z;
            s_pT[(16 + c4 + 3) * 128 + pix] = s1.w;
            s_pT[(32 + c4 + 0) * 128 + pix] = s2.x;
            s_pT[(32 + c4 + 1) * 128 + pix] = s2.y;
            s_pT[(32 + c4 + 2) * 128 + pix] = s2.z;
            s_pT[(32 + c4 + 3) * 128 + pix] = s2.w;
        }
        __syncthreads();

        // GEMM1: h[128 pix][128 e] = perc[128][48] @ f0[48][128] + b, relu
        // thread tile: 8 pixels x 8 e, accumulators packed over e-pairs
        int tx = t & 15, ty = t >> 4;
        int e0 = tx * 8, p0 = ty * 8;
        u64 acc2[8][4];
        {
            ulonglong2 b01 = __ldg((const ulonglong2*)&f0b[e0]);
            ulonglong2 b23 = __ldg((const ulonglong2*)&f0b[e0 + 4]);
#pragma unroll
            for (int i = 0; i < 8; i++) {
                acc2[i][0] = b01.x; acc2[i][1] = b01.y;
                acc2[i][2] = b23.x; acc2[i][3] = b23.y;
            }
        }

#pragma unroll 4
        for (int k = 0; k < 48; k++) {
            float4 pa = *(const float4*)&s_pT[k * 128 + p0];
            float4 pb = *(const float4*)&s_pT[k * 128 + p0 + 4];
            ulonglong2 wa = __ldg((const ulonglong2*)&f0w[k * 128 + e0]);
            ulonglong2 wb = __ldg((const ulonglong2*)&f0w[k * 128 + e0 + 4]);
            u64 pd[8] = {dup2(pa.x), dup2(pa.y), dup2(pa.z), dup2(pa.w),
                         dup2(pb.x), dup2(pb.y), dup2(pb.z), dup2(pb.w)};
#pragma unroll
            for (int i = 0; i < 8; i++) {
                fma2(acc2[i][0], pd[i], wa.x);
                fma2(acc2[i][1], pd[i], wa.y);
                fma2(acc2[i][2], pd[i], wb.x);
                fma2(acc2[i][3], pd[i], wb.y);
            }
        }
        __syncthreads();   // all s_pT reads done before s_h overlays it

#pragma unroll
        for (int i = 0; i < 8; i++) {
            float2 v0 = upk(acc2[i][0]), v1 = upk(acc2[i][1]);
            float2 v2 = upk(acc2[i][2]), v3 = upk(acc2[i][3]);
            float4 ha = make_float4(fmaxf(v0.x, 0.f), fmaxf(v0.y, 0.f),
                                    fmaxf(v1.x, 0.f), fmaxf(v1.y, 0.f));
            float4 hb = make_float4(fmaxf(v2.x, 0.f), fmaxf(v2.y, 0.f),
                                    fmaxf(v3.x, 0.f), fmaxf(v3.y, 0.f));
            *(float4*)&s_h[(p0 + i) * 132 + e0]     = ha;
            *(float4*)&s_h[(p0 + i) * 132 + e0 + 4] = hb;
        }
        __syncthreads();

        // GEMM2: dx[128][16] = h[128][128] @ f1[128][16]; thread: 1 pix x 8 outs
        {
            int pix = t >> 1, oo = (t & 1) * 8;
            u64 d2[4] = {0ull, 0ull, 0ull, 0ull};
#pragma unroll 4
            for (int k4 = 0; k4 < 32; k4++) {
                float4 hv4 = *(const float4*)&s_h[pix * 132 + k4 * 4];
                float hr[4] = {hv4.x, hv4.y, hv4.z, hv4.w};
#pragma unroll
                for (int kk = 0; kk < 4; kk++) {
                    int k = k4 * 4 + kk;
                    ulonglong2 w01 = __ldg((const ulonglong2*)&f1w[k * 16 + oo]);
                    ulonglong2 w23 = __ldg((const ulonglong2*)&f1w[k * 16 + oo + 4]);
                    u64 hd = dup2(hr[kk]);
                    fma2(d2[0], hd, w01.x);
                    fma2(d2[1], hd, w01.y);
                    fma2(d2[2], hd, w23.x);
                    fma2(d2[3], hd, w23.y);
                }
            }
            float2 u0 = upk(d2[0]), u1 = upk(d2[1]), u2 = upk(d2[2]), u3 = upk(d2[3]);
            *(float4*)&s_dx[pix * 16 + oo]     = make_float4(u0.x, u0.y, u1.x, u1.y);
            *(float4*)&s_dx[pix * 16 + oo + 4] = make_float4(u2.x, u2.y, u3.x, u3.y);
        }
        __syncthreads();

        if (t < 128) {
            int gp = P0 + t;
            uint2 r = d_threefry(key0, key1, 0u, (uint32_t)gp);
            uint32_t bits = r.x ^ r.y;
            float u = __uint_as_float((bits >> 9) | 0x3f800000u) - 1.0f;
            float lam = g_lam[rsel * NPIX + gp];
            float updf = (u < lam) ? 0.0f : 1.0f;

            int b = gp / 5184; int hw = gp - b * 5184;
            int h = hw / 72, w = hw - h * 72;
            float m = -3.4e38f;
#pragma unroll
            for (int i = 0; i < 3; i++) {
                int hh = h + i - 1;
                if ((unsigned)hh >= 72u) continue;
#pragma unroll
                for (int j = 0; j < 3; j++) {
                    int ww = w + j - 1;
                    if ((unsigned)ww >= 72u) continue;
                    m = fmaxf(m, x[((b * 5184 + hh * 72 + ww) << 4) + 3]);
                }
            }
            g_pre[gp] = (m > 0.1f) ? 1.f : 0.f;
            upd_slot[gp] = updf;

            const float4* __restrict__ xr = (const float4*)(x + (gp << 4));
            float4* __restrict__ xo = (float4*)(g_xn + (gp << 4));
#pragma unroll
            for (int q = 0; q < 4; q++) {
                float4 xv = xr[q];
                float4 dv = *(const float4*)&s_dx[t * 16 + q * 4];
                xv.x = fmaf(dv.x, updf, xv.x);
                xv.y = fmaf(dv.y, updf, xv.y);
                xv.z = fmaf(dv.z, updf, xv.z);
                xv.w = fmaf(dv.w, updf, xv.w);
                xo[q] = xv;
            }
        }
    }
}

// ============ fused kernel3: c2 (blocks [0,n_c2)) + life (rest) ============
__global__ void k_post(int n_c2,
                       const float* __restrict__ w2, const float* __restrict__ b2,
                       float* __restrict__ lam_slot, float* __restrict__ p_slot,
                       int wsel, int is_first,
                       float* __restrict__ xsteps_slot)
{
    __shared__ float ws[144];
    if ((int)blockIdx.x < n_c2) {
        if (threadIdx.x < 144) ws[threadIdx.x] = w2[threadIdx.x];
        __syncthreads();

        int p = blockIdx.x * 256 + threadIdx.x;
        int b = p / 5184; int hw = p - b * 5184;
        int h = hw / 72, w = hw - h * 72;

        float acc = b2[0];
#pragma unroll
        for (int i = 0; i < 3; i++) {
            int hh = h + i - 1;
            if ((unsigned)hh >= 72u) continue;
#pragma unroll
            for (int j = 0; j < 3; j++) {
                int ww = w + j - 1;
                if ((unsigned)ww >= 72u) continue;
                const float4* __restrict__ hp =
                    (const float4*)&g_h[(b * 5184 + hh * 72 + ww) << 4];
                const float* __restrict__ wp = ws + (i * 3 + j) * 16;
#pragma unroll
                for (int q = 0; q < 4; q++) {
                    float4 hv = hp[q];
                    acc = fmaf(hv.x, wp[q * 4 + 0], acc);
                    acc = fmaf(hv.y, wp[q * 4 + 1], acc);
                    acc = fmaf(hv.z, wp[q * 4 + 2], acc);
                    acc = fmaf(hv.w, wp[q * 4 + 3], acc);
                }
            }
        }
        float lam = 1.f / (1.f + expf(-acc));
        g_lam[wsel * NPIX + p] = lam;
        float un = is_first ? 1.0f : g_un[p];
        lam_slot[p] = lam;
        p_slot[p] = un * lam + 1e-6f;
        g_un[p] = un * (1.f - lam);
    } else {
        int p = ((int)blockIdx.x - n_c2) * 256 + threadIdx.x;
        int b = p / 5184; int hw = p - b * 5184;
        int h = hw / 72, w = hw - h * 72;
        float m = -3.4e38f;
#pragma unroll
        for (int i = 0; i < 3; i++) {
            int hh = h + i - 1;
            if ((unsigned)hh >= 72u) continue;
#pragma unroll
            for (int j = 0; j < 3; j++) {
                int ww = w + j - 1;
                if ((unsigned)ww >= 72u) continue;
                m = fmaxf(m, g_xn[((b * 5184 + hh * 72 + ww) << 4) + 3]);
            }
        }
        float life = ((m > 0.1f) && (g_pre[p] != 0.f)) ? 1.f : 0.f;
        const float4* __restrict__ xi = (const float4*)(g_xn + (p << 4));
        float4* __restrict__ xc = (float4*)(g_xcur + (p << 4));
        float4* __restrict__ xs = (float4*)(xsteps_slot + (p << 4));
#pragma unroll
        for (int q = 0; q < 4; q++) {
            float4 v = xi[q];
            v.x *= life; v.y *= life; v.z *= life; v.w *= life;
            xc[q] = v;
            xs[q] = v;
        }
    }
}

// ------- normalize p over the T axis (in-place in output region) -------
__global__ void k_pnorm(float* __restrict__ pbase) {
    int p = blockIdx.x * 256 + threadIdx.x;
    float s = 0.f;
#pragma unroll 8
    for (int t = 0; t < TT; t++) s += pbase[t * NPIX + p];
#pragma unroll 8
    for (int t = 0; t < TT; t++) pbase[t * NPIX + p] = pbase[t * NPIX + p] / s;
}

// ---------------- launch ----------------
extern "C" void kernel_launch(void* const* d_in, const int* in_sizes, int n_in,
                              void* d_out, int out_size) {
    (void)in_sizes; (void)n_in; (void)out_size;
    const float* x   = (const float*)d_in[0];
    const float* c1w = (const float*)d_in[1];
    const float* c1b = (const float*)d_in[2];
    const float* c2w = (const float*)d_in[3];
    const float* c2b = (const float*)d_in[4];
    const float* f0w = (const float*)d_in[5];
    const float* f0b = (const float*)d_in[6];
    const float* f1w = (const float*)d_in[7];

    float* out    = (float*)d_out;
    float* xsteps = out;                                  // (64, NPIX, 16)
    float* pout   = out + (size_t)TT * NPIX * 16;         // (64, NPIX)
    float* lamout = pout + (size_t)TT * NPIX;             // (64, NPIX)
    float* updout = lamout + (size_t)TT * NPIX;           // (64, NPIX)

    static int smem_set = 0;
    if (!smem_set) {
        cudaFuncSetAttribute(k_main, cudaFuncAttributeMaxDynamicSharedMemorySize, K2_SMEM);
        smem_set = 1;
    }

    // per-step keys: fold_in(key(42), k) = threefry((0,42),(0,k))
    uint32_t kk0[TT], kk1[TT];
    for (int n = 0; n < TT; n++) h_threefry(0u, 42u, 0u, (uint32_t)n, &kk0[n], &kk1[n]);

    const int NC1 = 192;   // 8 imgs * 24 row-triples
    const int NUP = 324;   // NPIX / 128

    // ---- step 0: update depends on THIS step's lambda -> strict order ----
    k_main<<<NC1, 256, K2_SMEM>>>(NC1, x, 1, c1w, c1b, f0w, f0b, f1w,
                                  updout, 0, kk0[0], kk1[0]);           // perc+c1
    k_post<<<162, 256>>>(162, c2w, c2b, lamout, pout, 0, 1, xsteps);    // c2 only
    k_main<<<NUP, 256, K2_SMEM>>>(0, x, 1, c1w, c1b, f0w, f0b, f1w,
                                  updout, 0, kk0[0], kk1[0]);           // perc+update
    k_post<<<162, 256>>>(0, c2w, c2b, lamout, pout, 0, 1, xsteps);      // life only

    // ---- steps 1..63: update uses PREVIOUS lambda -> c1 || update fused ----
    for (int k = 1; k < TT; k++) {
        int wsel = k & 1;
        int rsel = (k - 1) & 1;
        k_main<<<NC1 + NUP, 256, K2_SMEM>>>(NC1, x, 0, c1w, c1b, f0w, f0b, f1w,
                                            updout + (size_t)k * NPIX, rsel, kk0[k], kk1[k]);
        k_post<<<324, 256>>>(162, c2w, c2b,
                             lamout + (size_t)k * NPIX, pout + (size_t)k * NPIX,
                             wsel, 0, xsteps + (size_t)k * NPIX * 16);
    }
    k_pnorm<<<162, 256>>>(pout);
}